// round 7
// baseline (speedup 1.0000x reference)
#include <cuda_runtime.h>

// Problem constants
#define BB 16
#define TT 2048
#define DD 128
#define KK 2048
#define NCB 8
#define MM (BB*TT)          // 32768 rows
#define ROWS 128            // rows per block
#define KCH 64              // codewords per chunk
#define SAS 132             // sA row stride (floats)
#define SBS 68              // sB row stride (floats)

#define QELEMS (BB*DD*TT)           // 4194304
#define CELEMS (BB*NCB*TT)          // 262144

// Scratch (static device allocations are allowed)
__device__ float  g_residual[MM*DD];     // 16 MB, (B*T, D) row-major
__device__ float  g_cnorm[NCB*KK];       // ||c||^2 per codeword
__device__ double g_loss;

// ---------------------------------------------------------------------------
// f32x2 packed helpers (sm_100+). Bit-identical rounding to scalar fmaf.
// ---------------------------------------------------------------------------
__device__ __forceinline__ unsigned long long dup2(float a) {
    unsigned long long r;
    asm("mov.b64 %0, {%1, %1};" : "=l"(r) : "f"(a));
    return r;
}
__device__ __forceinline__ void ffma2(unsigned long long& d,
                                      unsigned long long a,
                                      unsigned long long b) {
    asm("fma.rn.f32x2 %0, %1, %2, %0;" : "+l"(d) : "l"(a), "l"(b));
}
__device__ __forceinline__ float2 unpk2(unsigned long long v) {
    float2 f;
    asm("mov.b64 {%0, %1}, %2;" : "=f"(f.x), "=f"(f.y) : "l"(v));
    return f;
}

// ---------------------------------------------------------------------------
// init: residual[(b*T+t)*D + d] = x[b*D*T + d*T + t]; zero loss accumulator
// ---------------------------------------------------------------------------
__global__ void rvq_init_kernel(const float* __restrict__ x) {
    int i = blockIdx.x * blockDim.x + threadIdx.x;
    if (i == 0) g_loss = 0.0;
    if (i < MM * DD) {
        int m = i >> 7;          // row  (b*T+t)
        int d = i & 127;
        int b = m >> 11;
        int t = m & (TT - 1);
        g_residual[i] = x[((size_t)b * DD + d) * TT + t];
    }
}

// ---------------------------------------------------------------------------
// cnorm: one warp per codeword row (all 8 stages at once)
// ---------------------------------------------------------------------------
__global__ void rvq_cnorm_kernel(const float* __restrict__ cbs) {
    int gw   = (blockIdx.x * blockDim.x + threadIdx.x) >> 5;
    int lane = threadIdx.x & 31;
    if (gw >= NCB * KK) return;
    const float* row = cbs + (size_t)gw * DD;
    float s = 0.f;
    #pragma unroll
    for (int d = lane; d < DD; d += 32) {
        float v = row[d];
        s = fmaf(v, v, s);
    }
    #pragma unroll
    for (int o = 16; o; o >>= 1) s += __shfl_xor_sync(0xffffffffu, s, o);
    if (lane == 0) g_cnorm[gw] = s;
}

// ---------------------------------------------------------------------------
// Fused stage kernel. Block = 256 threads owns 128 rows; B chunk = 64 cwds.
// Per-thread tile: 8 rows x 4 cols.
//   rows = ty*4+{0..3} and 64+ty*4+{0..3}  (packed as 64-bit pairs from sA)
//   cols = tx*4+{0..3}                      (b values duplicated via dup2)
// smem = sA(128x132) + sB(128x68) = 100 KB  -> 2 blocks/SM, 16 warps/SM.
// ---------------------------------------------------------------------------
__global__ void __launch_bounds__(256, 2)
rvq_stage_kernel(const float* __restrict__ cb,      // stage codebook (K, D)
                 float* __restrict__ codes_out,     // out + QELEMS
                 int stage) {
    extern __shared__ float smem[];
    float* sA = smem;                 // 128*SAS
    float* sB = smem + ROWS * SAS;    // 128*SBS

    const int tid  = threadIdx.x;
    const int tx   = tid & 15;        // col-group id (4 cols)
    const int ty   = tid >> 4;        // row-group id (8 rows, split 4+4)
    const int row0 = blockIdx.x * ROWS;

    // ---- Load A tile transposed: sA[d][m] ----
    {
        const float4* src = (const float4*)(g_residual + (size_t)row0 * DD);
        #pragma unroll
        for (int it = 0; it < 16; ++it) {
            int i  = tid + it * 256;        // 0..4095
            int m  = i & 127;
            int dq = i >> 7;                // 0..31 (float4 index within row)
            float4 v = src[m * 32 + dq];
            int sb = (dq * 4) * SAS + m;    // conflict-free STS
            sA[sb]           = v.x;
            sA[sb + SAS]     = v.y;
            sA[sb + 2 * SAS] = v.z;
            sA[sb + 3 * SAS] = v.w;
        }
    }

    float bestv[8];
    int   besti[8];
    #pragma unroll
    for (int r = 0; r < 8; ++r) { bestv[r] = 3.402823466e38f; besti[r] = 0; }

    const float* cn_stage = g_cnorm + stage * KK;

    for (int ch = 0; ch < KK / KCH; ++ch) {
        __syncthreads();   // sB safe to overwrite
        // ---- Load B chunk transposed: sB[d][n], n < 64 ----
        {
            const float4* bsrc = (const float4*)(cb + (size_t)(ch * KCH) * DD);
            #pragma unroll
            for (int it = 0; it < 8; ++it) {
                int i  = tid + it * 256;        // 0..2047
                int n  = i & 63;
                int dq = i >> 6;                // 0..31
                float4 v = bsrc[n * 32 + dq];
                int sb = (dq * 4) * SBS + n;    // conflict-free STS
                sB[sb]           = v.x;
                sB[sb + SBS]     = v.y;
                sB[sb + 2 * SBS] = v.z;
                sB[sb + 3 * SBS] = v.w;
            }
        }
        __syncthreads();

        // ---- 128x64x128 register-tiled dot products (f32x2 packed FMA) ----
        // acc[p][c]: p = row pair (2 rows), c = column tx*4+c
        unsigned long long acc[4][4];
        #pragma unroll
        for (int p = 0; p < 4; ++p)
            #pragma unroll
            for (int c = 0; c < 4; ++c) acc[p][c] = 0ull;

        #pragma unroll 8
        for (int k = 0; k < DD; ++k) {
            const float* ka = &sA[k * SAS];
            const float* kb = &sB[k * SBS];
            ulonglong2 aq0 = *(const ulonglong2*)&ka[ty << 2];        // rows ty*4+{0,1},{2,3}
            ulonglong2 aq1 = *(const ulonglong2*)&ka[64 + (ty << 2)]; // rows 64+ty*4+...
            float4 bv = *(const float4*)&kb[tx << 2];
            unsigned long long bd0 = dup2(bv.x);
            unsigned long long bd1 = dup2(bv.y);
            unsigned long long bd2 = dup2(bv.z);
            unsigned long long bd3 = dup2(bv.w);
            unsigned long long ap[4] = {aq0.x, aq0.y, aq1.x, aq1.y};
            #pragma unroll
            for (int p = 0; p < 4; ++p) {
                ffma2(acc[p][0], ap[p], bd0);
                ffma2(acc[p][1], ap[p], bd1);
                ffma2(acc[p][2], ap[p], bd2);
                ffma2(acc[p][3], ap[p], bd3);
            }
        }

        // ---- scores = cnorm - 2*dot ; running argmin ----
        float4 cn = *(const float4*)(cn_stage + ch * KCH + (tx << 2));
        float cna[4] = {cn.x, cn.y, cn.z, cn.w};
        int nbase = ch * KCH + (tx << 2);
        #pragma unroll
        for (int p = 0; p < 4; ++p) {
            #pragma unroll
            for (int c = 0; c < 4; ++c) {
                float2 v = unpk2(acc[p][c]);        // rows 2p, 2p+1
                float dlo = fmaf(-2.f, v.x, cna[c]);
                float dhi = fmaf(-2.f, v.y, cna[c]);
                int idx = nbase + c;
                if (dlo < bestv[2 * p])     { bestv[2 * p]     = dlo; besti[2 * p]     = idx; }
                if (dhi < bestv[2 * p + 1]) { bestv[2 * p + 1] = dhi; besti[2 * p + 1] = idx; }
            }
        }
    }

    // ---- cross-thread argmin reduce (reuse sB) ----
    __syncthreads();
    float* redv = sB;
    int*   redi = (int*)(sB + ROWS * 16);
    #pragma unroll
    for (int lr = 0; lr < 8; ++lr) {
        int m = (lr < 4) ? (ty << 2) + lr : 64 + (ty << 2) + (lr - 4);
        redv[m * 16 + tx] = bestv[lr];
        redi[m * 16 + tx] = besti[lr];
    }
    __syncthreads();

    __shared__ int s_bidx[ROWS];
    if (tid < ROWS) {
        float bv = 3.402823466e38f;
        int   bi = 1 << 30;
        #pragma unroll
        for (int j = 0; j < 16; ++j) {
            float v  = redv[tid * 16 + j];
            int   ix = redi[tid * 16 + j];
            if (v < bv || (v == bv && ix < bi)) { bv = v; bi = ix; }
        }
        s_bidx[tid] = bi;
        int gm = row0 + tid;
        int b  = gm >> 11;
        int t  = gm & (TT - 1);
        codes_out[(size_t)b * (NCB * TT) + (size_t)stage * TT + t] = (float)bi;
    }
    __syncthreads();

    // ---- residual update + loss: 2 threads per row (64 d each) ----
    {
        int m    = tid >> 1;
        int half = tid & 1;
        int bi   = s_bidx[m];
        const float4* crow = (const float4*)(cb + (size_t)bi * DD + half * 64);
        float* gres = g_residual + ((size_t)(row0 + m)) * DD + half * 64;
        float ss = 0.f;
        #pragma unroll
        for (int q = 0; q < 16; ++q) {
            float4 c4 = crow[q];
            int d = half * 64 + q * 4;
            float r0 = sA[(d + 0) * SAS + m] - c4.x;
            float r1 = sA[(d + 1) * SAS + m] - c4.y;
            float r2 = sA[(d + 2) * SAS + m] - c4.z;
            float r3 = sA[(d + 3) * SAS + m] - c4.w;
            ((float4*)gres)[q] = make_float4(r0, r1, r2, r3);
            ss = fmaf(r0, r0, ss);
            ss = fmaf(r1, r1, ss);
            ss = fmaf(r2, r2, ss);
            ss = fmaf(r3, r3, ss);
        }
        #pragma unroll
        for (int o = 16; o; o >>= 1) ss += __shfl_xor_sync(0xffffffffu, ss, o);
        __shared__ float s_ws[8];
        int wid = tid >> 5, lane = tid & 31;
        if (lane == 0) s_ws[wid] = ss;
        __syncthreads();
        if (tid == 0) {
            float s = 0.f;
            #pragma unroll
            for (int w = 0; w < 8; ++w) s += s_ws[w];
            atomicAdd(&g_loss, (double)s);
        }
    }
}

// ---------------------------------------------------------------------------
// finalize: total_quantized = x - residual_final (transposed back), + loss
// ---------------------------------------------------------------------------
__global__ void rvq_final_kernel(const float* __restrict__ x,
                                 float* __restrict__ out) {
    int i = blockIdx.x * blockDim.x + threadIdx.x;
    if (i < QELEMS) {
        int t = i & (TT - 1);
        int d = (i >> 11) & (DD - 1);
        int b = i >> 18;
        out[i] = x[i] - g_residual[((size_t)(b * TT + t)) * DD + d];
    }
    if (i == 0) {
        out[QELEMS + CELEMS] = (float)(g_loss / (double)(MM * DD));
    }
}

// ---------------------------------------------------------------------------
extern "C" void kernel_launch(void* const* d_in, const int* in_sizes, int n_in,
                              void* d_out, int out_size) {
    const float* x   = (const float*)d_in[0];
    const float* cbs = (const float*)d_in[1];
    // Defensive input-order check by element count
    if (n_in >= 2 && in_sizes[0] == NCB * KK * DD && in_sizes[1] == QELEMS) {
        const float* tmp = x; x = cbs; cbs = tmp;
    }
    float* out = (float*)d_out;

    const int smem_bytes = (ROWS * SAS + ROWS * SBS) * (int)sizeof(float); // 102400
    static bool attr_set = false;
    if (!attr_set) {
        cudaFuncSetAttribute(rvq_stage_kernel,
                             cudaFuncAttributeMaxDynamicSharedMemorySize,
                             smem_bytes);
        attr_set = true;
    }

    rvq_init_kernel<<<(MM * DD + 255) / 256, 256>>>(x);
    rvq_cnorm_kernel<<<(NCB * KK * 32 + 255) / 256, 256>>>(cbs);

    for (int s = 0; s < NCB; ++s) {
        rvq_stage_kernel<<<MM / ROWS, 256, smem_bytes>>>(
            cbs + (size_t)s * KK * DD, out + QELEMS, s);
    }

    rvq_final_kernel<<<(QELEMS + 255) / 256, 256>>>(x, out);
}